// round 15
// baseline (speedup 1.0000x reference)
#include <cuda_runtime.h>
#include <cstdint>

typedef unsigned int u32;
typedef unsigned short u16;

#define KCODES 1024
#define DIM 64
#define NROWS 65536
#define THREADS 512
#define NIT 64           // GEMM iterations (2 tiles of 8 codes each)
#define CAP 20           // candidate cap per row (overflow -> exact full scan)
#define NCTA 152         // one CTA per SM; warp-granular work units
#define NUNITS 2048      // 65536 rows / 32

#define SZ   21.0f       // z scale (|z| <= 6.05 unclamped)
#define SE   130048.0f   // E scale (127*1024)
#define SZSE 2731008.0f  // SZ*SE

// Scratch (no device allocation allowed -> __device__ globals)
__device__ int    g_counts[KCODES];
__device__ float  g_Esq[KCODES];
__device__ int    g_EsqhInt[KCODES];
__device__ float  g_El1[KCODES];
__device__ double g_loss;
__device__ int    g_done;
__device__ __align__(16) u32 g_Eq8[KCODES * 16];  // int8-packed codebook (x SE)

// ---------------------------------------------------------------------------
// SMEM layout (bytes). E rows 16 u32 (64B) in PERMUTED frag order:
//   word j of a code row stored at pos (j&3)*4 + (j>>2), so a lane's 4 frag
//   words {(l&3), (l&3)+4, (l&3)+8, (l&3)+12} are one aligned LDS.128.
//   16-u32 rows are conflict-free for this pattern (phase = 2 codes = 32 banks).
// ---------------------------------------------------------------------------
#define SE_OFF    0          // E s8 [1024][16 u32]               65536
#define SQ_OFF    65536      // esq f32 [1024]                     4096
#define SQI_OFF   69632      // esq/2*SZSE s32 [1024]              4096
#define SCAND_OFF 73728      // cand u16 [512][CAP]               20480
#define SCNT_OFF  94208      // counts int [512]                   2048
#define SMX_OFF   96256      // misc f32 [16] (el1max / loss)        64
#define SMEM_SZ   96320

// ---------------------------------------------------------------------------
// Kernel 1: esq (exact fp32 sequential chain - DO NOT reorder, bit-feeds the
// verified d chain) + int8-pack E + per-code L1 + zero accumulators.
// ---------------------------------------------------------------------------
__global__ void prep_kernel(const float* __restrict__ E) {
    int k = blockIdx.x * 32 + threadIdx.x;
    if (k < KCODES) {
        float e[64];
        const float4* er = (const float4*)(E + k * DIM);
        #pragma unroll
        for (int i = 0; i < 16; i++) {
            float4 v = er[i];
            e[4*i] = v.x; e[4*i+1] = v.y; e[4*i+2] = v.z; e[4*i+3] = v.w;
        }
        float s = 0.f;
        #pragma unroll
        for (int d = 0; d < 64; d++) s = fmaf(e[d], e[d], s);
        g_Esq[k] = s;
        g_EsqhInt[k] = __float2int_rn(s * 0.5f * SZSE);
        float l1 = 0.f;
        #pragma unroll
        for (int d = 0; d < 64; d++) l1 += fabsf(e[d]);
        g_El1[k] = l1;
        g_counts[k] = 0;
        #pragma unroll
        for (int j = 0; j < 16; j++) {
            u32 wv = 0;
            #pragma unroll
            for (int m = 0; m < 4; m++) {
                float q = fminf(fmaxf(e[4*j + m] * SE, -127.f), 127.f);
                int iv = __float2int_rn(q);
                wv |= ((u32)iv & 0xFFu) << (8 * m);
            }
            g_Eq8[k * 16 + j] = wv;
        }
    }
    if (k == 0) { g_loss = 0.0; g_done = 0; }
}

// ---------------------------------------------------------------------------
// m16n8k32 s8 mma, s32 accumulate (base PTX since sm_80 -> safe on sm_103)
// ---------------------------------------------------------------------------
__device__ __forceinline__ void mma_s8(int d[4], const u32 a[4], u32 b0, u32 b1) {
    asm("mma.sync.aligned.m16n8k32.row.col.s32.s8.s8.s32 "
        "{%0,%1,%2,%3}, {%4,%5,%6,%7}, {%8,%9}, {%0,%1,%2,%3};"
        : "+r"(d[0]), "+r"(d[1]), "+r"(d[2]), "+r"(d[3])
        : "r"(a[0]), "r"(a[1]), "r"(a[2]), "r"(a[3]), "r"(b0), "r"(b1));
}

// ---------------------------------------------------------------------------
// Kernel 2: warp-autonomous 32-row units (unit = blockIdx + 152*warp).
// INT8 IMMA two-pass argmax on s'_int = z8.e8 - esqh_int (exact s32):
//   pass 1: per-row int max (B-LDS pipelined); pass 2: collect vs
//   rmax - M_int, with RIGOROUS quantization margin
//   m = 0.5*sz*Sum|z| + 0.5*se*Sum|e|max + 16  (int units), M = 3m + 2.
// -> warp-local exact refine (R2 bit chain, fp32 E) -> fused gather/loss.
// ---------------------------------------------------------------------------
__global__ void __launch_bounds__(THREADS, 1)
vq_main(const float* __restrict__ in, const float* __restrict__ E,
        float* __restrict__ out) {
    extern __shared__ __align__(16) char S[];
    u32*   sE    = (u32*)(S + SE_OFF);
    float* sq    = (float*)(S + SQ_OFF);
    int*   sqi   = (int*)(S + SQI_OFF);
    u16*   scand = (u16*)(S + SCAND_OFF);
    int*   scnt  = (int*)(S + SCNT_OFF);
    float* smx   = (float*)(S + SMX_OFF);
    __shared__ int s_islast;

    const int t = threadIdx.x;
    const int w = t >> 5, l = t & 31;
    const int gw = blockIdx.x + NCTA * w;   // this warp's 32-row unit
    const bool act = (gw < NUNITS);
    const int n = gw * 32 + l;              // this lane's row (valid iff act)
    const int b = n >> 10, p = n & 1023;
    const float* zrow = in + b * 65536 + p; // deref'd only when act

    // --- stage E int8 permuted: dst word (j&3)*4+(j>>2) <- word j ---
    {
        const uint4* esrc = (const uint4*)g_Eq8;   // 4096 uint4
        #pragma unroll
        for (int i = 0; i < 8; i++) {
            int lin = t + i * 512;
            int code = lin >> 2, q = lin & 3;      // uint4 q = words 4q..4q+3
            uint4 v = esrc[lin];
            u32* dst = sE + code * 16 + q;
            dst[0]  = v.x;
            dst[4]  = v.y;
            dst[8]  = v.z;
            dst[12] = v.w;
        }
    }
    // --- esq (fp32 + int halves) + block max of code L1 norms ---
    float em = 0.f;
    #pragma unroll
    for (int i = 0; i < 2; i++) {
        int k = t + i * 512;
        sq[k]  = g_Esq[k];
        sqi[k] = g_EsqhInt[k];
        em = fmaxf(em, g_El1[k]);
    }
    #pragma unroll
    for (int o = 16; o; o >>= 1) em = fmaxf(em, __shfl_xor_sync(0xffffffffu, em, o));
    if (l == 0) smx[w] = em;
    scnt[t] = 0;
    __syncthreads();

    float el1max = smx[0];
    #pragma unroll
    for (int i = 1; i < 16; i++) el1max = fmaxf(el1max, smx[i]);

    float ls = 0.f;    // loss partial (0 for inactive warps)

    if (act) {
        // --- z row -> regs: zsq exact chain (dims 0..63 sequential, R2 order),
        //     L1 accumulation, int8 quantization (x SZ, clamped) ---
        u32 zq8[16];
        float zsq = 0.f, zl1 = 0.f;
        u32 cur = 0;
        #pragma unroll
        for (int c = 0; c < 64; c++) {
            float v = __ldg(zrow + c * 1024);
            zsq = fmaf(v, v, zsq);
            zl1 += fabsf(v);
            float qf = fminf(fmaxf(v * SZ, -127.f), 127.f);
            int iv = __float2int_rn(qf);
            cur |= ((u32)iv & 0xFFu) << (8 * (c & 3));
            if ((c & 3) == 3) { zq8[c >> 2] = cur; cur = 0; }
        }

        // --- A fragments via intra-warp shfl (unit rows = this warp's lanes).
        //     m16n8k32 A: a0=word(l&3)@r0, a1=same@r1, a2=word 4+(l&3)@r0,
        //     a3=@r1; kstep1 uses words 8+,12+. ---
        u32 A[2][2][4];
        #pragma unroll
        for (int m = 0; m < 2; m++) {
            const int s0 = m * 16 + (l >> 2);
            const int s1 = s0 + 8;
            #pragma unroll
            for (int c = 0; c < 4; c++) {
                u32 w0a = __shfl_sync(0xffffffffu, zq8[c],      s0);
                u32 w0b = __shfl_sync(0xffffffffu, zq8[c],      s1);
                u32 w1a = __shfl_sync(0xffffffffu, zq8[4 + c],  s0);
                u32 w1b = __shfl_sync(0xffffffffu, zq8[4 + c],  s1);
                u32 w2a = __shfl_sync(0xffffffffu, zq8[8 + c],  s0);
                u32 w2b = __shfl_sync(0xffffffffu, zq8[8 + c],  s1);
                u32 w3a = __shfl_sync(0xffffffffu, zq8[12 + c], s0);
                u32 w3b = __shfl_sync(0xffffffffu, zq8[12 + c], s1);
                if ((l & 3) == c) {
                    A[m][0][0] = w0a; A[m][0][1] = w0b;
                    A[m][0][2] = w1a; A[m][0][3] = w1b;
                    A[m][1][0] = w2a; A[m][1][1] = w2b;
                    A[m][1][2] = w3a; A[m][1][3] = w3b;
                }
            }
        }

        // --- per-thread row slots; margin from shfl'd zl1 ---
        int srow[4], rmax[4], Mi[4];
        #pragma unroll
        for (int m = 0; m < 2; m++)
            #pragma unroll
            for (int rh = 0; rh < 2; rh++) {
                int s = m * 2 + rh;
                int lane = m * 16 + (l >> 2) + 8 * rh;
                srow[s] = w * 32 + lane;
                float zl1r = __shfl_sync(0xffffffffu, zl1, lane);
                // m (int units) = 0.5*SZ*zl1 + 0.5*SE*el1max + 16; M = 3m+2
                Mi[s] = (int)(3.0f * (10.5f * zl1r + 65024.0f * el1max + 16.0f)) + 2;
                rmax[s] = (int)0x80000000;
            }

        const int bbase = (l >> 2) * 16 + (l & 3) * 4;   // per-thread B offset

        // ============ PASS 1: int max of s'; B double-buffer pipelined ======
        {
            uint4 cx = *(const uint4*)(sE + bbase);
            uint4 cy = *(const uint4*)(sE + bbase + 128);
            for (int it = 0; it < NIT; it++) {
                const int nit = (it + 1 < NIT) ? (it + 1) : it;
                const u32* np = sE + bbase + nit * 256;
                uint4 nx = *(const uint4*)(np);
                uint4 ny = *(const uint4*)(np + 128);

                int D0a[4] = {0,0,0,0}, D1a[4] = {0,0,0,0};
                int D0b[4] = {0,0,0,0}, D1b[4] = {0,0,0,0};
                mma_s8(D0a, A[0][0], cx.x, cx.y);   // 4 independent chains,
                mma_s8(D1a, A[1][0], cx.x, cx.y);   // depth 2 each
                mma_s8(D0b, A[0][0], cy.x, cy.y);
                mma_s8(D1b, A[1][0], cy.x, cy.y);
                mma_s8(D0a, A[0][1], cx.z, cx.w);
                mma_s8(D1a, A[1][1], cx.z, cx.w);
                mma_s8(D0b, A[0][1], cy.z, cy.w);
                mma_s8(D1b, A[1][1], cy.z, cy.w);

                const int k0a = it * 16 + (l & 3) * 2;
                const int k0b = k0a + 8;
                const int ha0 = sqi[k0a], ha1 = sqi[k0a + 1];
                const int hb0 = sqi[k0b], hb1 = sqi[k0b + 1];
                #pragma unroll
                for (int m = 0; m < 2; m++) {
                    const int* Da = m ? D1a : D0a;
                    const int* Db = m ? D1b : D0b;
                    #pragma unroll
                    for (int rh = 0; rh < 2; rh++) {
                        const int s = m * 2 + rh;
                        int s0 = Da[rh * 2]     - ha0;
                        int s1 = Da[rh * 2 + 1] - ha1;
                        int s2 = Db[rh * 2]     - hb0;
                        int s3 = Db[rh * 2 + 1] - hb1;
                        rmax[s] = max(rmax[s], max(max(s0, s1), max(s2, s3)));
                    }
                }
                cx = nx; cy = ny;
            }
        }
        // final per-row max across the 4 sibling lanes; integer threshold
        int thr4[4];
        #pragma unroll
        for (int s = 0; s < 4; s++) {
            int v = rmax[s];
            v = max(v, __shfl_xor_sync(0xffffffffu, v, 1));
            v = max(v, __shfl_xor_sync(0xffffffffu, v, 2));
            thr4[s] = v - Mi[s];
        }

        // ============ PASS 2: recompute + collect vs final threshold ========
        {
            uint4 cx = *(const uint4*)(sE + bbase);
            uint4 cy = *(const uint4*)(sE + bbase + 128);
            for (int it = 0; it < NIT; it++) {
                const int nit = (it + 1 < NIT) ? (it + 1) : it;
                const u32* np = sE + bbase + nit * 256;
                uint4 nx = *(const uint4*)(np);
                uint4 ny = *(const uint4*)(np + 128);

                int D0a[4] = {0,0,0,0}, D1a[4] = {0,0,0,0};
                int D0b[4] = {0,0,0,0}, D1b[4] = {0,0,0,0};
                mma_s8(D0a, A[0][0], cx.x, cx.y);
                mma_s8(D1a, A[1][0], cx.x, cx.y);
                mma_s8(D0b, A[0][0], cy.x, cy.y);
                mma_s8(D1b, A[1][0], cy.x, cy.y);
                mma_s8(D0a, A[0][1], cx.z, cx.w);
                mma_s8(D1a, A[1][1], cx.z, cx.w);
                mma_s8(D0b, A[0][1], cy.z, cy.w);
                mma_s8(D1b, A[1][1], cy.z, cy.w);

                const int k0a = it * 16 + (l & 3) * 2;
                const int k0b = k0a + 8;
                const int ha0 = sqi[k0a], ha1 = sqi[k0a + 1];
                const int hb0 = sqi[k0b], hb1 = sqi[k0b + 1];
                #pragma unroll
                for (int m = 0; m < 2; m++) {
                    const int* Da = m ? D1a : D0a;
                    const int* Db = m ? D1b : D0b;
                    #pragma unroll
                    for (int rh = 0; rh < 2; rh++) {
                        const int s = m * 2 + rh;
                        int s0 = Da[rh * 2]     - ha0;
                        int s1 = Da[rh * 2 + 1] - ha1;
                        int s2 = Db[rh * 2]     - hb0;
                        int s3 = Db[rh * 2 + 1] - hb1;
                        if (s0 >= thr4[s]) {
                            int ix = atomicAdd(&scnt[srow[s]], 1);
                            if (ix < CAP) scand[srow[s] * CAP + ix] = (u16)k0a;
                        }
                        if (s1 >= thr4[s]) {
                            int ix = atomicAdd(&scnt[srow[s]], 1);
                            if (ix < CAP) scand[srow[s] * CAP + ix] = (u16)(k0a + 1);
                        }
                        if (s2 >= thr4[s]) {
                            int ix = atomicAdd(&scnt[srow[s]], 1);
                            if (ix < CAP) scand[srow[s] * CAP + ix] = (u16)k0b;
                        }
                        if (s3 >= thr4[s]) {
                            int ix = atomicAdd(&scnt[srow[s]], 1);
                            if (ix < CAP) scand[srow[s] * CAP + ix] = (u16)(k0b + 1);
                        }
                    }
                }
                cx = nx; cy = ny;
            }
        }
        // Warp-local sync suffices: this warp's rows written only by its lanes.
        __syncwarp();

        // --- exact refine (lane l <-> row n). R2 bit chain + tie-break. ---
        float zv[64];
        #pragma unroll
        for (int c = 0; c < 64; c++) zv[c] = __ldg(zrow + c * 1024);

        const int cr = scnt[t];
        float best = 3.4e38f;
        int bi = 0;
        const int full = (cr > CAP);        // astronomically rare; still correct
        const int nev = full ? KCODES : cr;
        for (int i = 0; i < nev; i++) {
            const int k = full ? i : (int)scand[t * CAP + i];
            const float4* er = (const float4*)(E + k * 64);
            float c0 = 0.f, c1 = 0.f, c2 = 0.f, c3 = 0.f;
            #pragma unroll
            for (int j = 0; j < 16; j++) {
                float4 e4 = __ldg(er + j);
                c0 = fmaf(zv[4*j],     e4.x, c0);
                c1 = fmaf(zv[4*j + 1], e4.y, c1);
                c2 = fmaf(zv[4*j + 2], e4.z, c2);
                c3 = fmaf(zv[4*j + 3], e4.w, c3);
            }
            float s = __fadd_rn(__fadd_rn(c0, c2), __fadd_rn(c1, c3));
            float d = __fmaf_rn(-2.0f, s, __fadd_rn(zsq, sq[k]));
            if (d < best || (d == best && k < bi)) { best = d; bi = k; }
        }
        atomicAdd(&g_counts[bi], 1);

        // --- fused gather Zq + loss (bit-mimicking fl(z + fl(e - z))) ---
        float* zq = out + 1 + b * 65536 + p;
        const float4* er = (const float4*)(E + bi * 64);
        #pragma unroll
        for (int j = 0; j < 16; j++) {
            float4 e4 = __ldg(er + j);
            float ev[4] = {e4.x, e4.y, e4.z, e4.w};
            #pragma unroll
            for (int m = 0; m < 4; m++) {
                float z = zv[4*j + m];
                float diff = __fsub_rn(ev[m], z);
                ls = fmaf(diff, diff, ls);
                zq[(4*j + m) * 1024] = __fadd_rn(z, diff);
            }
        }
    }

    // --- loss reduction (inactive warps contribute 0) ---
    #pragma unroll
    for (int o = 16; o; o >>= 1) ls += __shfl_xor_sync(0xffffffffu, ls, o);
    __syncthreads();                 // el1max reads long done; reuse smx
    if (l == 0) smx[w] = ls;
    __syncthreads();
    if (t == 0) {
        float s = 0.f;
        #pragma unroll
        for (int i = 0; i < 16; i++) s += smx[i];
        atomicAdd(&g_loss, (double)s);
        __threadfence();
        int old = atomicAdd(&g_done, 1);
        s_islast = (old == NCTA - 1);
    }
    __syncthreads();

    // --- last CTA: finalize (perplexity + scalars) ---
    if (s_islast) {
        __threadfence();
        float v = 0.f;
        #pragma unroll
        for (int i = 0; i < 2; i++) {
            int k = t + i * 512;
            float cnt = (float)g_counts[k];
            float pr = cnt * (1.0f / 65536.0f);
            v = fmaf(pr, log2f(pr + 1e-10f), v);
        }
        #pragma unroll
        for (int o = 16; o; o >>= 1) v += __shfl_xor_sync(0xffffffffu, v, o);
        if (l == 0) smx[w] = v;
        __syncthreads();
        if (t == 0) {
            float x = 0.f;
            #pragma unroll
            for (int i = 0; i < 16; i++) x += smx[i];
            float entropy = -x;
            float perp = exp2f(entropy);
            float lv = (float)(g_loss * (1.0 / 4194304.0));
            out[0] = lv + 0.25f * lv;
            out[1 + NROWS * DIM]     = lv;
            out[1 + NROWS * DIM + 1] = lv;
            out[1 + NROWS * DIM + 2] = perp;
            g_done = 0;              // reset for graph replay determinism
        }
    }
}

// ---------------------------------------------------------------------------
extern "C" void kernel_launch(void* const* d_in, const int* in_sizes, int n_in,
                              void* d_out, int out_size) {
    const float* in = (const float*)d_in[0];
    const float* E  = (const float*)d_in[1];
    float* out = (float*)d_out;

    cudaFuncSetAttribute(vq_main, cudaFuncAttributeMaxDynamicSharedMemorySize,
                         SMEM_SZ);
    prep_kernel<<<32, 32>>>(E);
    vq_main<<<NCTA, THREADS, SMEM_SZ>>>(in, E, out);
}

// round 16
// speedup vs baseline: 8.3292x; 8.3292x over previous
#include <cuda_runtime.h>
#include <cstdint>

typedef unsigned int u32;
typedef unsigned short u16;

#define KCODES 1024
#define DIM 64
#define NROWS 65536
#define THREADS 448      // 14 warps; reg cap 146 (was 128 at 512thr)
#define NWARP 14
#define NT 128           // n-tiles of 8 codes
#define NIT (NT / 2)     // GEMM iterations (2 tiles each)
#define CAP 16           // candidate cap per row (overflow -> exact full scan)
#define NCTA 152         // one CTA per SM; warp-granular work units
#define NUNITS 2048      // 65536 rows / 32

// Scratch (no device allocation allowed -> __device__ globals)
__device__ int    g_counts[KCODES];
__device__ float  g_Esq[KCODES];
__device__ double g_loss;
__device__ int    g_done;
__device__ __align__(16) u32 g_Ebf[KCODES * 32];  // bf16x2-packed codebook

// ---------------------------------------------------------------------------
// SMEM layout (bytes). E rows 36 u32 (144B) in PERMUTED frag order:
//   sE[code*36 + (j&3)*8 + q] holds original k-pair u32 j = 4q + (j&3),
// so one lane's 8 B-frag words for a tile are 8 contiguous u32 -> 2x LDS.128.
// ---------------------------------------------------------------------------
#define SE_OFF    0          // E bf16 [1024][36 u32]            147456
#define SQ_OFF    147456     // esq f32 [1024]                     4096
#define SQH_OFF   151552     // esq/2 f32 [1024]                   4096
#define SCAND_OFF 155648     // cand u16 [448][CAP]               14336
#define SCNT_OFF  169984     // counts int [448]                   1792
#define SMX_OFF   171776     // misc f32 [14] (emax / loss)          64
#define SMEM_SZ   171840

// ---------------------------------------------------------------------------
// Kernel 1: esq (exact fp32 sequential chain - DO NOT reorder, bit-feeds the
// verified d chain) + bf16x2-pack E + zero accumulators. 32x32 for latency.
// ---------------------------------------------------------------------------
__global__ void prep_kernel(const float* __restrict__ E) {
    int k = blockIdx.x * 32 + threadIdx.x;
    if (k < KCODES) {
        float e[64];
        const float4* er = (const float4*)(E + k * DIM);
        #pragma unroll
        for (int i = 0; i < 16; i++) {
            float4 v = er[i];
            e[4*i] = v.x; e[4*i+1] = v.y; e[4*i+2] = v.z; e[4*i+3] = v.w;
        }
        float s = 0.f;
        #pragma unroll
        for (int d = 0; d < 64; d++) s = fmaf(e[d], e[d], s);
        g_Esq[k] = s;
        g_counts[k] = 0;
        #pragma unroll
        for (int i = 0; i < 32; i++) {
            u32 pr;  // lo = dim 2i, hi = dim 2i+1
            asm("cvt.rn.bf16x2.f32 %0, %1, %2;" : "=r"(pr) : "f"(e[2*i+1]), "f"(e[2*i]));
            g_Ebf[k * 32 + i] = pr;
        }
    }
    if (k == 0) { g_loss = 0.0; g_done = 0; }
}

// ---------------------------------------------------------------------------
// m16n8k16 bf16 mma, fp32 accumulate (REAL HMMA on sm_103; int8/tf32 legacy
// mma.sync are EMULATED on Blackwell - R15 lesson, do not use)
// ---------------------------------------------------------------------------
__device__ __forceinline__ void mma16816(float d[4], const u32 a[4], const u32 b[2]) {
    asm("mma.sync.aligned.m16n8k16.row.col.f32.bf16.bf16.f32 "
        "{%0,%1,%2,%3}, {%4,%5,%6,%7}, {%8,%9}, {%0,%1,%2,%3};"
        : "+f"(d[0]), "+f"(d[1]), "+f"(d[2]), "+f"(d[3])
        : "r"(a[0]), "r"(a[1]), "r"(a[2]), "r"(a[3]), "r"(b[0]), "r"(b[1]));
}

// ---------------------------------------------------------------------------
// Kernel 2: warp-autonomous 32-row units (unit = blockIdx + 152*warp).
// bf16 HMMA two-pass argmax; 8 independent depth-2 MMA chains per iteration
// (ks{0,1} / ks{2,3} split, fp32-merged in epilogue) to halve exposed MMA
// latency. Pass 1: per-row max (B-LDS pipelined); pass 2: collect vs final
// max - margin'. -> warp-local exact refine (R2 bit chain) -> fused
// gather/loss. Last-CTA finalize.
// ---------------------------------------------------------------------------
__global__ void __launch_bounds__(THREADS, 1)
vq_main(const float* __restrict__ in, const float* __restrict__ E,
        float* __restrict__ out) {
    extern __shared__ __align__(16) char S[];
    u32*   sE    = (u32*)(S + SE_OFF);
    float* sq    = (float*)(S + SQ_OFF);
    float* sqh   = (float*)(S + SQH_OFF);
    u16*   scand = (u16*)(S + SCAND_OFF);
    int*   scnt  = (int*)(S + SCNT_OFF);
    float* smx   = (float*)(S + SMX_OFF);
    __shared__ int s_islast;

    const int t = threadIdx.x;
    const int w = t >> 5, l = t & 31;
    const int gw = blockIdx.x + NCTA * w;   // this warp's 32-row unit
    const bool act = (gw < NUNITS);
    const int n = gw * 32 + l;              // this lane's row (valid iff act)
    const int b = n >> 10, p = n & 1023;
    const float* zrow = in + b * 65536 + p; // deref'd only when act

    // --- stage E permuted: sE[code*36 + c*8 + q] = component c of uint4 q ---
    {
        const uint4* esrc = (const uint4*)g_Ebf;
        for (int lin = t; lin < 8192; lin += THREADS) {
            int code = lin >> 3, q = lin & 7;
            uint4 v = esrc[lin];
            u32* dst = sE + code * 36 + q;
            dst[0]  = v.x;
            dst[8]  = v.y;
            dst[16] = v.z;
            dst[24] = v.w;
        }
    }
    // --- esq (+half) + block max ---
    float em = 0.f;
    for (int k = t; k < KCODES; k += THREADS) {
        float v = g_Esq[k];
        sq[k] = v;
        sqh[k] = 0.5f * v;
        em = fmaxf(em, v);
    }
    #pragma unroll
    for (int o = 16; o; o >>= 1) em = fmaxf(em, __shfl_xor_sync(0xffffffffu, em, o));
    if (l == 0) smx[w] = em;
    scnt[t] = 0;
    __syncthreads();

    float emax = smx[0];
    #pragma unroll
    for (int i = 1; i < NWARP; i++) emax = fmaxf(emax, smx[i]);

    float ls = 0.f;    // loss partial (0 for inactive warps)

    if (act) {
        // --- z row -> regs: zsq exact chain (dims 0..63 sequential, R2 order),
        //     bf16x2 pack kept in regs (zb) for shfl-based A-frag build ---
        u32 zb[32];
        float zsq = 0.f, prev = 0.f;
        #pragma unroll
        for (int c = 0; c < 64; c++) {
            float v = __ldg(zrow + c * 1024);
            zsq = fmaf(v, v, zsq);
            if (c & 1) {
                u32 pr;  // lo = even dim, hi = odd dim
                asm("cvt.rn.bf16x2.f32 %0, %1, %2;" : "=r"(pr) : "f"(v), "f"(prev));
                zb[c >> 1] = pr;
            } else prev = v;
        }

        // --- A fragments via intra-warp shfl: unit rows are this warp's lanes ---
        u32 A[2][4][4];
        #pragma unroll
        for (int m = 0; m < 2; m++)
            #pragma unroll
            for (int ks = 0; ks < 4; ks++) {
                const int s0 = m * 16 + (l >> 2);
                const int s1 = s0 + 8;
                u32 a0 = 0, a1 = 0, a2 = 0, a3 = 0;
                #pragma unroll
                for (int c = 0; c < 4; c++) {
                    u32 v0 = __shfl_sync(0xffffffffu, zb[ks * 8 + c],     s0);
                    u32 v1 = __shfl_sync(0xffffffffu, zb[ks * 8 + c],     s1);
                    u32 v2 = __shfl_sync(0xffffffffu, zb[ks * 8 + c + 4], s0);
                    u32 v3 = __shfl_sync(0xffffffffu, zb[ks * 8 + c + 4], s1);
                    if ((l & 3) == c) { a0 = v0; a1 = v1; a2 = v2; a3 = v3; }
                }
                A[m][ks][0] = a0; A[m][ks][1] = a1;
                A[m][ks][2] = a2; A[m][ks][3] = a3;
            }

        // --- per-thread row slots (D-frag rows); szq via shfl ---
        int   srow[4];          // LOCAL slot index (w*32 + lane-of-row)
        float szq4[4], rmax[4];
        #pragma unroll
        for (int m = 0; m < 2; m++)
            #pragma unroll
            for (int rh = 0; rh < 2; rh++) {
                int s = m * 2 + rh;
                int lane = m * 16 + (l >> 2) + 8 * rh;
                srow[s] = w * 32 + lane;
                szq4[s] = __shfl_sync(0xffffffffu, zsq, lane);
                rmax[s] = -3.4e38f;
            }

        const int bbase = (l >> 2) * 36 + (l & 3) * 8;   // per-thread B offset

        // ============ PASS 1: bf16 max of s'; 8 depth-2 chains ==============
        {
            uint4 cx0 = *(const uint4*)(sE + bbase);
            uint4 cx1 = *(const uint4*)(sE + bbase + 4);
            uint4 cy0 = *(const uint4*)(sE + bbase + 288);
            uint4 cy1 = *(const uint4*)(sE + bbase + 292);
            for (int it = 0; it < NIT; it++) {
                const int nit = (it + 1 < NIT) ? (it + 1) : it;
                const u32* np = sE + bbase + nit * 576;
                uint4 nx0 = *(const uint4*)(np);
                uint4 nx1 = *(const uint4*)(np + 4);
                uint4 ny0 = *(const uint4*)(np + 288);
                uint4 ny1 = *(const uint4*)(np + 292);

                u32 B0[4][2] = {{cx0.x,cx0.y},{cx0.z,cx0.w},{cx1.x,cx1.y},{cx1.z,cx1.w}};
                u32 B1[4][2] = {{cy0.x,cy0.y},{cy0.z,cy0.w},{cy1.x,cy1.y},{cy1.z,cy1.w}};
                // 8 independent chains of depth 2 (split ks{0,1} / ks{2,3})
                float P0a[4] = {0,0,0,0}, Q0a[4] = {0,0,0,0};
                float P1a[4] = {0,0,0,0}, Q1a[4] = {0,0,0,0};
                float P0b[4] = {0,0,0,0}, Q0b[4] = {0,0,0,0};
                float P1b[4] = {0,0,0,0}, Q1b[4] = {0,0,0,0};
                mma16816(P0a, A[0][0], B0[0]);
                mma16816(P1a, A[1][0], B0[0]);
                mma16816(P0b, A[0][0], B1[0]);
                mma16816(P1b, A[1][0], B1[0]);
                mma16816(Q0a, A[0][2], B0[2]);
                mma16816(Q1a, A[1][2], B0[2]);
                mma16816(Q0b, A[0][2], B1[2]);
                mma16816(Q1b, A[1][2], B1[2]);
                mma16816(P0a, A[0][1], B0[1]);
                mma16816(P1a, A[1][1], B0[1]);
                mma16816(P0b, A[0][1], B1[1]);
                mma16816(P1b, A[1][1], B1[1]);
                mma16816(Q0a, A[0][3], B0[3]);
                mma16816(Q1a, A[1][3], B0[3]);
                mma16816(Q0b, A[0][3], B1[3]);
                mma16816(Q1b, A[1][3], B1[3]);

                const int k0a = it * 16 + (l & 3) * 2;
                const int k0b = k0a + 8;
                const float ha0 = sqh[k0a], ha1 = sqh[k0a + 1];
                const float hb0 = sqh[k0b], hb1 = sqh[k0b + 1];
                #pragma unroll
                for (int m = 0; m < 2; m++) {
                    const float* Pa = m ? P1a : P0a;
                    const float* Qa = m ? Q1a : Q0a;
                    const float* Pb = m ? P1b : P0b;
                    const float* Qb = m ? Q1b : Q0b;
                    #pragma unroll
                    for (int rh = 0; rh < 2; rh++) {
                        const int s = m * 2 + rh;
                        float s0 = (Pa[rh * 2]     + Qa[rh * 2])     - ha0;
                        float s1 = (Pa[rh * 2 + 1] + Qa[rh * 2 + 1]) - ha1;
                        float s2 = (Pb[rh * 2]     + Qb[rh * 2])     - hb0;
                        float s3 = (Pb[rh * 2 + 1] + Qb[rh * 2 + 1]) - hb1;
                        rmax[s] = fmaxf(rmax[s],
                                        fmaxf(fmaxf(s0, s1), fmaxf(s2, s3)));
                    }
                }
                cx0 = nx0; cx1 = nx1; cy0 = ny0; cy1 = ny1;
            }
        }
        // final per-row max across the 4 sibling lanes; threshold in s'-domain:
        // collect s' >= max - marg', marg' = marg/2 (d = zsq + 2*(esq/2 - s')).
        float thr4[4];
        #pragma unroll
        for (int s = 0; s < 4; s++) {
            float v = rmax[s];
            v = fmaxf(v, __shfl_xor_sync(0xffffffffu, v, 1));
            v = fmaxf(v, __shfl_xor_sync(0xffffffffu, v, 2));
            thr4[s] = v - 0.01f * sqrtf(szq4[s] * emax);
        }

        // ============ PASS 2: recompute + collect vs final threshold ========
        {
            uint4 cx0 = *(const uint4*)(sE + bbase);
            uint4 cx1 = *(const uint4*)(sE + bbase + 4);
            uint4 cy0 = *(const uint4*)(sE + bbase + 288);
            uint4 cy1 = *(const uint4*)(sE + bbase + 292);
            for (int it = 0; it < NIT; it++) {
                const int nit = (it + 1 < NIT) ? (it + 1) : it;
                const u32* np = sE + bbase + nit * 576;
                uint4 nx0 = *(const uint4*)(np);
                uint4 nx1 = *(const uint4*)(np + 4);
                uint4 ny0 = *(const uint4*)(np + 288);
                uint4 ny1 = *(const uint4*)(np + 292);

                u32 B0[4][2] = {{cx0.x,cx0.y},{cx0.z,cx0.w},{cx1.x,cx1.y},{cx1.z,cx1.w}};
                u32 B1[4][2] = {{cy0.x,cy0.y},{cy0.z,cy0.w},{cy1.x,cy1.y},{cy1.z,cy1.w}};
                float P0a[4] = {0,0,0,0}, Q0a[4] = {0,0,0,0};
                float P1a[4] = {0,0,0,0}, Q1a[4] = {0,0,0,0};
                float P0b[4] = {0,0,0,0}, Q0b[4] = {0,0,0,0};
                float P1b[4] = {0,0,0,0}, Q1b[4] = {0,0,0,0};
                mma16816(P0a, A[0][0], B0[0]);
                mma16816(P1a, A[1][0], B0[0]);
                mma16816(P0b, A[0][0], B1[0]);
                mma16816(P1b, A[1][0], B1[0]);
                mma16816(Q0a, A[0][2], B0[2]);
                mma16816(Q1a, A[1][2], B0[2]);
                mma16816(Q0b, A[0][2], B1[2]);
                mma16816(Q1b, A[1][2], B1[2]);
                mma16816(P0a, A[0][1], B0[1]);
                mma16816(P1a, A[1][1], B0[1]);
                mma16816(P0b, A[0][1], B1[1]);
                mma16816(P1b, A[1][1], B1[1]);
                mma16816(Q0a, A[0][3], B0[3]);
                mma16816(Q1a, A[1][3], B0[3]);
                mma16816(Q0b, A[0][3], B1[3]);
                mma16816(Q1b, A[1][3], B1[3]);

                const int k0a = it * 16 + (l & 3) * 2;
                const int k0b = k0a + 8;
                const float ha0 = sqh[k0a], ha1 = sqh[k0a + 1];
                const float hb0 = sqh[k0b], hb1 = sqh[k0b + 1];
                #pragma unroll
                for (int m = 0; m < 2; m++) {
                    const float* Pa = m ? P1a : P0a;
                    const float* Qa = m ? Q1a : Q0a;
                    const float* Pb = m ? P1b : P0b;
                    const float* Qb = m ? Q1b : Q0b;
                    #pragma unroll
                    for (int rh = 0; rh < 2; rh++) {
                        const int s = m * 2 + rh;
                        float s0 = (Pa[rh * 2]     + Qa[rh * 2])     - ha0;
                        float s1 = (Pa[rh * 2 + 1] + Qa[rh * 2 + 1]) - ha1;
                        float s2 = (Pb[rh * 2]     + Qb[rh * 2])     - hb0;
                        float s3 = (Pb[rh * 2 + 1] + Qb[rh * 2 + 1]) - hb1;
                        if (s0 >= thr4[s]) {
                            int ix = atomicAdd(&scnt[srow[s]], 1);
                            if (ix < CAP) scand[srow[s] * CAP + ix] = (u16)k0a;
                        }
                        if (s1 >= thr4[s]) {
                            int ix = atomicAdd(&scnt[srow[s]], 1);
                            if (ix < CAP) scand[srow[s] * CAP + ix] = (u16)(k0a + 1);
                        }
                        if (s2 >= thr4[s]) {
                            int ix = atomicAdd(&scnt[srow[s]], 1);
                            if (ix < CAP) scand[srow[s] * CAP + ix] = (u16)k0b;
                        }
                        if (s3 >= thr4[s]) {
                            int ix = atomicAdd(&scnt[srow[s]], 1);
                            if (ix < CAP) scand[srow[s] * CAP + ix] = (u16)(k0b + 1);
                        }
                    }
                }
                cx0 = nx0; cx1 = nx1; cy0 = ny0; cy1 = ny1;
            }
        }
        // Warp-local sync suffices: this warp's rows written only by its lanes.
        __syncwarp();

        // --- exact refine (lane l <-> row n). R2 bit chain + tie-break. ---
        float zv[64];
        #pragma unroll
        for (int c = 0; c < 64; c++) zv[c] = __ldg(zrow + c * 1024);

        const int cr = scnt[t];
        float best = 3.4e38f;
        int bi = 0;
        const int full = (cr > CAP);        // astronomically rare; still correct
        const int nev = full ? KCODES : cr;
        for (int i = 0; i < nev; i++) {
            const int k = full ? i : (int)scand[t * CAP + i];
            const float4* er = (const float4*)(E + k * 64);
            float c0 = 0.f, c1 = 0.f, c2 = 0.f, c3 = 0.f;
            #pragma unroll
            for (int j = 0; j < 16; j++) {
                float4 e4 = __ldg(er + j);
                c0 = fmaf(zv[4*j],     e4.x, c0);
                c1 = fmaf(zv[4*j + 1], e4.y, c1);
                c2 = fmaf(zv[4*j + 2], e4.z, c2);
                c3 = fmaf(zv[4*j + 3], e4.w, c3);
            }
            float s = __fadd_rn(__fadd_rn(c0, c2), __fadd_rn(c1, c3));
            float d = __fmaf_rn(-2.0f, s, __fadd_rn(zsq, sq[k]));
            if (d < best || (d == best && k < bi)) { best = d; bi = k; }
        }
        atomicAdd(&g_counts[bi], 1);

        // --- fused gather Zq + loss (bit-mimicking fl(z + fl(e - z))) ---
        float* zq = out + 1 + b * 65536 + p;
        const float4* er = (const float4*)(E + bi * 64);
        #pragma unroll
        for (int j = 0; j < 16; j++) {
            float4 e4 = __ldg(er + j);
            float ev[4] = {e4.x, e4.y, e4.z, e4.w};
            #pragma unroll
            for (int m = 0; m < 4; m++) {
                float z = zv[4*j + m];
                float diff = __fsub_rn(ev[m], z);
                ls = fmaf(diff, diff, ls);
                zq[(4*j + m) * 1024] = __fadd_rn(z, diff);
            }
        }
    }

    // --- loss reduction (inactive warps contribute 0) ---
    #pragma unroll
    for (int o = 16; o; o >>= 1) ls += __shfl_xor_sync(0xffffffffu, ls, o);
    __syncthreads();                 // emax reads long done; reuse smx
    if (l == 0) smx[w] = ls;
    __syncthreads();
    if (t == 0) {
        float s = 0.f;
        #pragma unroll
        for (int i = 0; i < NWARP; i++) s += smx[i];
        atomicAdd(&g_loss, (double)s);
        __threadfence();
        int old = atomicAdd(&g_done, 1);
        s_islast = (old == NCTA - 1);
    }
    __syncthreads();

    // --- last CTA: finalize (perplexity + scalars) ---
    if (s_islast) {
        __threadfence();
        float v = 0.f;
        for (int k = t; k < KCODES; k += THREADS) {
            float cnt = (float)g_counts[k];
            float pr = cnt * (1.0f / 65536.0f);
            v = fmaf(pr, log2f(pr + 1e-10f), v);
        }
        #pragma unroll
        for (int o = 16; o; o >>= 1) v += __shfl_xor_sync(0xffffffffu, v, o);
        if (l == 0) smx[w] = v;
        __syncthreads();
        if (t == 0) {
            float x = 0.f;
            #pragma unroll
            for (int i = 0; i < NWARP; i++) x += smx[i];
            float entropy = -x;
            float perp = exp2f(entropy);
            float lv = (float)(g_loss * (1.0 / 4194304.0));
            out[0] = lv + 0.25f * lv;
            out[1 + NROWS * DIM]     = lv;
            out[1 + NROWS * DIM + 1] = lv;
            out[1 + NROWS * DIM + 2] = perp;
            g_done = 0;              // reset for graph replay determinism
        }
    }
}

// ---------------------------------------------------------------------------
extern "C" void kernel_launch(void* const* d_in, const int* in_sizes, int n_in,
                              void* d_out, int out_size) {
    const float* in = (const float*)d_in[0];
    const float* E  = (const float*)d_in[1];
    float* out = (float*)d_out;

    cudaFuncSetAttribute(vq_main, cudaFuncAttributeMaxDynamicSharedMemorySize,
                         SMEM_SZ);
    prep_kernel<<<32, 32>>>(E);
    vq_main<<<NCTA, THREADS, SMEM_SZ>>>(in, E, out);
}

// round 17
// speedup vs baseline: 9.7616x; 1.1720x over previous
#include <cuda_runtime.h>
#include <cstdint>

typedef unsigned int u32;
typedef unsigned short u16;

#define KCODES 1024
#define DIM 64
#define NROWS 65536
#define THREADS 512
#define NWARP 16
#define NIT 64           // GEMM iterations (2 tiles of 8 codes each)
#define REPLAY 8         // first REPLAY iters replayed vs final threshold
#define CAP 24           // candidate cap per row (overflow -> exact full scan)
#define NCTA 152         // one CTA per SM; warp-granular work units
#define NUNITS 2048      // 65536 rows / 32

// Scratch (no device allocation allowed -> __device__ globals)
__device__ int    g_counts[KCODES];
__device__ float  g_Esq[KCODES];
__device__ double g_loss;
__device__ int    g_done;
__device__ __align__(16) u32 g_Ebf[KCODES * 32];  // bf16x2-packed codebook

// ---------------------------------------------------------------------------
// SMEM layout (bytes). E rows 36 u32 (144B) in PERMUTED frag order:
//   sE[code*36 + (j&3)*8 + q] holds original k-pair u32 j = 4q + (j&3),
// so one lane's 8 B-frag words for a tile are 8 contiguous u32 -> 2x LDS.128.
// ---------------------------------------------------------------------------
#define SE_OFF    0          // E bf16 [1024][36 u32]            147456
#define SQ_OFF    147456     // esq f32 [1024]                     4096
#define SQH_OFF   151552     // esq/2 f32 [1024]                   4096
#define SCAND_OFF 155648     // cand u16 [512][CAP]               24576
#define SCNT_OFF  180224     // counts int [512]                   2048
#define SMX_OFF   182272     // misc f32 [16] (emax / loss)          64
#define SMEM_SZ   182336

// ---------------------------------------------------------------------------
// Kernel 1: esq (exact fp32 sequential chain - DO NOT reorder, bit-feeds the
// verified d chain) + bf16x2-pack E + zero accumulators. 32x32 for latency.
// ---------------------------------------------------------------------------
__global__ void prep_kernel(const float* __restrict__ E) {
    int k = blockIdx.x * 32 + threadIdx.x;
    if (k < KCODES) {
        float e[64];
        const float4* er = (const float4*)(E + k * DIM);
        #pragma unroll
        for (int i = 0; i < 16; i++) {
            float4 v = er[i];
            e[4*i] = v.x; e[4*i+1] = v.y; e[4*i+2] = v.z; e[4*i+3] = v.w;
        }
        float s = 0.f;
        #pragma unroll
        for (int d = 0; d < 64; d++) s = fmaf(e[d], e[d], s);
        g_Esq[k] = s;
        g_counts[k] = 0;
        #pragma unroll
        for (int i = 0; i < 32; i++) {
            u32 pr;  // lo = dim 2i, hi = dim 2i+1
            asm("cvt.rn.bf16x2.f32 %0, %1, %2;" : "=r"(pr) : "f"(e[2*i+1]), "f"(e[2*i]));
            g_Ebf[k * 32 + i] = pr;
        }
    }
    if (k == 0) { g_loss = 0.0; g_done = 0; }
}

// ---------------------------------------------------------------------------
// m16n8k16 bf16 mma, fp32 accumulate (REAL HMMA on sm_103; int8/tf32 legacy
// mma.sync are EMULATED on Blackwell - R15 lesson, do not use)
// ---------------------------------------------------------------------------
__device__ __forceinline__ void mma16816(float d[4], const u32 a[4], const u32 b[2]) {
    asm("mma.sync.aligned.m16n8k16.row.col.f32.bf16.bf16.f32 "
        "{%0,%1,%2,%3}, {%4,%5,%6,%7}, {%8,%9}, {%0,%1,%2,%3};"
        : "+f"(d[0]), "+f"(d[1]), "+f"(d[2]), "+f"(d[3])
        : "r"(a[0]), "r"(a[1]), "r"(a[2]), "r"(a[3]), "r"(b[0]), "r"(b[1]));
}

// ---------------------------------------------------------------------------
// Kernel 2: warp-autonomous 32-row units (unit = blockIdx + 152*warp).
// SINGLE fused bf16 HMMA pass (argmax domain, s' = z.e - esq/2):
//   - rmax updated every iter; quad max + threshold refresh every 4 iters
//   - collection enabled for it >= 8 vs the (stale, hence conservative)
//     threshold; iters 0..7 replayed afterwards vs the FINAL threshold
// -> warp-local exact refine (R2 bit chain) -> fused gather/loss.
// ---------------------------------------------------------------------------
__global__ void __launch_bounds__(THREADS, 1)
vq_main(const float* __restrict__ in, const float* __restrict__ E,
        float* __restrict__ out) {
    extern __shared__ __align__(16) char S[];
    u32*   sE    = (u32*)(S + SE_OFF);
    float* sq    = (float*)(S + SQ_OFF);
    float* sqh   = (float*)(S + SQH_OFF);
    u16*   scand = (u16*)(S + SCAND_OFF);
    int*   scnt  = (int*)(S + SCNT_OFF);
    float* smx   = (float*)(S + SMX_OFF);
    __shared__ int s_islast;

    const int t = threadIdx.x;
    const int w = t >> 5, l = t & 31;
    const int gw = blockIdx.x + NCTA * w;   // this warp's 32-row unit
    const bool act = (gw < NUNITS);
    const int n = gw * 32 + l;              // this lane's row (valid iff act)
    const int b = n >> 10, p = n & 1023;
    const float* zrow = in + b * 65536 + p; // deref'd only when act

    // --- stage E permuted: sE[code*36 + c*8 + q] = component c of uint4 q ---
    {
        const uint4* esrc = (const uint4*)g_Ebf;
        #pragma unroll
        for (int i = 0; i < 16; i++) {
            int lin = t + i * 512;              // uint4 index
            int code = lin >> 3, q = lin & 7;
            uint4 v = esrc[lin];
            u32* dst = sE + code * 36 + q;
            dst[0]  = v.x;
            dst[8]  = v.y;
            dst[16] = v.z;
            dst[24] = v.w;
        }
    }
    // --- esq (+half) + block max ---
    float em = 0.f;
    #pragma unroll
    for (int i = 0; i < 2; i++) {
        int k = t + i * 512;
        float v = g_Esq[k];
        sq[k] = v;
        sqh[k] = 0.5f * v;
        em = fmaxf(em, v);
    }
    #pragma unroll
    for (int o = 16; o; o >>= 1) em = fmaxf(em, __shfl_xor_sync(0xffffffffu, em, o));
    if (l == 0) smx[w] = em;
    scnt[t] = 0;
    __syncthreads();

    float emax = smx[0];
    #pragma unroll
    for (int i = 1; i < NWARP; i++) emax = fmaxf(emax, smx[i]);

    float ls = 0.f;    // loss partial (0 for inactive warps)

    if (act) {
        // --- z row -> regs: zsq exact chain (dims 0..63 sequential, R2 order),
        //     bf16x2 pack kept in regs (zb) for shfl-based A-frag build ---
        u32 zb[32];
        float zsq = 0.f, prev = 0.f;
        #pragma unroll
        for (int c = 0; c < 64; c++) {
            float v = __ldg(zrow + c * 1024);
            zsq = fmaf(v, v, zsq);
            if (c & 1) {
                u32 pr;  // lo = even dim, hi = odd dim
                asm("cvt.rn.bf16x2.f32 %0, %1, %2;" : "=r"(pr) : "f"(v), "f"(prev));
                zb[c >> 1] = pr;
            } else prev = v;
        }

        // --- A fragments via intra-warp shfl: unit rows are this warp's lanes ---
        u32 A[2][4][4];
        #pragma unroll
        for (int m = 0; m < 2; m++)
            #pragma unroll
            for (int ks = 0; ks < 4; ks++) {
                const int s0 = m * 16 + (l >> 2);
                const int s1 = s0 + 8;
                u32 a0 = 0, a1 = 0, a2 = 0, a3 = 0;
                #pragma unroll
                for (int c = 0; c < 4; c++) {
                    u32 v0 = __shfl_sync(0xffffffffu, zb[ks * 8 + c],     s0);
                    u32 v1 = __shfl_sync(0xffffffffu, zb[ks * 8 + c],     s1);
                    u32 v2 = __shfl_sync(0xffffffffu, zb[ks * 8 + c + 4], s0);
                    u32 v3 = __shfl_sync(0xffffffffu, zb[ks * 8 + c + 4], s1);
                    if ((l & 3) == c) { a0 = v0; a1 = v1; a2 = v2; a3 = v3; }
                }
                A[m][ks][0] = a0; A[m][ks][1] = a1;
                A[m][ks][2] = a2; A[m][ks][3] = a3;
            }

        // --- per-thread row slots (D-frag rows); szq via shfl ---
        int   srow[4];          // LOCAL slot index (w*32 + lane-of-row)
        float szq4[4], marg[4], rmax[4], thr4[4];
        #pragma unroll
        for (int m = 0; m < 2; m++)
            #pragma unroll
            for (int rh = 0; rh < 2; rh++) {
                int s = m * 2 + rh;
                int lane = m * 16 + (l >> 2) + 8 * rh;
                srow[s] = w * 32 + lane;
                szq4[s] = __shfl_sync(0xffffffffu, zsq, lane);
                // marg' = 0.01*sqrt(zsq*emax) (s'-domain; 2x conservative)
                marg[s] = 0.01f * sqrtf(szq4[s] * emax);
                rmax[s] = -3.4e38f;
                thr4[s] = 3.4e38f;   // collection disabled until first refresh
            }

        const int bbase = (l >> 2) * 36 + (l & 3) * 8;   // per-thread B offset

        // ============ FUSED PASS: max + collect (it>=8); B pipelined ========
        {
            uint4 cx0 = *(const uint4*)(sE + bbase);
            uint4 cx1 = *(const uint4*)(sE + bbase + 4);
            uint4 cy0 = *(const uint4*)(sE + bbase + 288);
            uint4 cy1 = *(const uint4*)(sE + bbase + 292);
            for (int it = 0; it < NIT; it++) {
                const int nit = (it + 1 < NIT) ? (it + 1) : it;
                const u32* np = sE + bbase + nit * 576;
                uint4 nx0 = *(const uint4*)(np);
                uint4 nx1 = *(const uint4*)(np + 4);
                uint4 ny0 = *(const uint4*)(np + 288);
                uint4 ny1 = *(const uint4*)(np + 292);

                u32 B0[4][2] = {{cx0.x,cx0.y},{cx0.z,cx0.w},{cx1.x,cx1.y},{cx1.z,cx1.w}};
                u32 B1[4][2] = {{cy0.x,cy0.y},{cy0.z,cy0.w},{cy1.x,cy1.y},{cy1.z,cy1.w}};
                float D0a[4] = {0,0,0,0}, D1a[4] = {0,0,0,0};
                float D0b[4] = {0,0,0,0}, D1b[4] = {0,0,0,0};
                #pragma unroll
                for (int ks = 0; ks < 4; ks++) {   // 4 independent chains
                    mma16816(D0a, A[0][ks], B0[ks]);
                    mma16816(D1a, A[1][ks], B0[ks]);
                    mma16816(D0b, A[0][ks], B1[ks]);
                    mma16816(D1b, A[1][ks], B1[ks]);
                }
                const int k0a = it * 16 + (l & 3) * 2;
                const int k0b = k0a + 8;
                const float ha0 = sqh[k0a], ha1 = sqh[k0a + 1];
                const float hb0 = sqh[k0b], hb1 = sqh[k0b + 1];
                #pragma unroll
                for (int m = 0; m < 2; m++) {
                    const float* Da = m ? D1a : D0a;
                    const float* Db = m ? D1b : D0b;
                    #pragma unroll
                    for (int rh = 0; rh < 2; rh++) {
                        const int s = m * 2 + rh;
                        float s0 = Da[rh * 2]     - ha0;
                        float s1 = Da[rh * 2 + 1] - ha1;
                        float s2 = Db[rh * 2]     - hb0;
                        float s3 = Db[rh * 2 + 1] - hb1;
                        if (it >= REPLAY) {   // stale thr -> conservative
                            if (s0 >= thr4[s]) {
                                int ix = atomicAdd(&scnt[srow[s]], 1);
                                if (ix < CAP) scand[srow[s] * CAP + ix] = (u16)k0a;
                            }
                            if (s1 >= thr4[s]) {
                                int ix = atomicAdd(&scnt[srow[s]], 1);
                                if (ix < CAP) scand[srow[s] * CAP + ix] = (u16)(k0a + 1);
                            }
                            if (s2 >= thr4[s]) {
                                int ix = atomicAdd(&scnt[srow[s]], 1);
                                if (ix < CAP) scand[srow[s] * CAP + ix] = (u16)k0b;
                            }
                            if (s3 >= thr4[s]) {
                                int ix = atomicAdd(&scnt[srow[s]], 1);
                                if (ix < CAP) scand[srow[s] * CAP + ix] = (u16)(k0b + 1);
                            }
                        }
                        rmax[s] = fmaxf(rmax[s],
                                        fmaxf(fmaxf(s0, s1), fmaxf(s2, s3)));
                    }
                }
                // quad max + threshold refresh every 4 iters (it=63 -> final)
                if ((it & 3) == 3) {
                    #pragma unroll
                    for (int s = 0; s < 4; s++) {
                        float v = rmax[s];
                        v = fmaxf(v, __shfl_xor_sync(0xffffffffu, v, 1));
                        v = fmaxf(v, __shfl_xor_sync(0xffffffffu, v, 2));
                        rmax[s] = v;
                        thr4[s] = v - marg[s];
                    }
                }
                cx0 = nx0; cx1 = nx1; cy0 = ny0; cy1 = ny1;
            }
        }

        // ============ REPLAY iters 0..7 vs FINAL threshold ==================
        for (int it = 0; it < REPLAY; it++) {
            const u32* cp = sE + bbase + it * 576;
            uint4 cx0 = *(const uint4*)(cp);
            uint4 cx1 = *(const uint4*)(cp + 4);
            uint4 cy0 = *(const uint4*)(cp + 288);
            uint4 cy1 = *(const uint4*)(cp + 292);
            u32 B0[4][2] = {{cx0.x,cx0.y},{cx0.z,cx0.w},{cx1.x,cx1.y},{cx1.z,cx1.w}};
            u32 B1[4][2] = {{cy0.x,cy0.y},{cy0.z,cy0.w},{cy1.x,cy1.y},{cy1.z,cy1.w}};
            float D0a[4] = {0,0,0,0}, D1a[4] = {0,0,0,0};
            float D0b[4] = {0,0,0,0}, D1b[4] = {0,0,0,0};
            #pragma unroll
            for (int ks = 0; ks < 4; ks++) {
                mma16816(D0a, A[0][ks], B0[ks]);
                mma16816(D1a, A[1][ks], B0[ks]);
                mma16816(D0b, A[0][ks], B1[ks]);
                mma16816(D1b, A[1][ks], B1[ks]);
            }
            const int k0a = it * 16 + (l & 3) * 2;
            const int k0b = k0a + 8;
            const float ha0 = sqh[k0a], ha1 = sqh[k0a + 1];
            const float hb0 = sqh[k0b], hb1 = sqh[k0b + 1];
            #pragma unroll
            for (int m = 0; m < 2; m++) {
                const float* Da = m ? D1a : D0a;
                const float* Db = m ? D1b : D0b;
                #pragma unroll
                for (int rh = 0; rh < 2; rh++) {
                    const int s = m * 2 + rh;
                    float s0 = Da[rh * 2]     - ha0;
                    float s1 = Da[rh * 2 + 1] - ha1;
                    float s2 = Db[rh * 2]     - hb0;
                    float s3 = Db[rh * 2 + 1] - hb1;
                    if (s0 >= thr4[s]) {
                        int ix = atomicAdd(&scnt[srow[s]], 1);
                        if (ix < CAP) scand[srow[s] * CAP + ix] = (u16)k0a;
                    }
                    if (s1 >= thr4[s]) {
                        int ix = atomicAdd(&scnt[srow[s]], 1);
                        if (ix < CAP) scand[srow[s] * CAP + ix] = (u16)(k0a + 1);
                    }
                    if (s2 >= thr4[s]) {
                        int ix = atomicAdd(&scnt[srow[s]], 1);
                        if (ix < CAP) scand[srow[s] * CAP + ix] = (u16)k0b;
                    }
                    if (s3 >= thr4[s]) {
                        int ix = atomicAdd(&scnt[srow[s]], 1);
                        if (ix < CAP) scand[srow[s] * CAP + ix] = (u16)(k0b + 1);
                    }
                }
            }
        }
        // Warp-local sync suffices: this warp's rows written only by its lanes.
        __syncwarp();

        // --- exact refine (lane l <-> row n). R2 bit chain + tie-break. ---
        float zv[64];
        #pragma unroll
        for (int c = 0; c < 64; c++) zv[c] = __ldg(zrow + c * 1024);

        const int cr = scnt[t];
        float best = 3.4e38f;
        int bi = 0;
        const int full = (cr > CAP);        // astronomically rare; still correct
        const int nev = full ? KCODES : cr;
        for (int i = 0; i < nev; i++) {
            const int k = full ? i : (int)scand[t * CAP + i];
            const float4* er = (const float4*)(E + k * 64);
            float c0 = 0.f, c1 = 0.f, c2 = 0.f, c3 = 0.f;
            #pragma unroll
            for (int j = 0; j < 16; j++) {
                float4 e4 = __ldg(er + j);
                c0 = fmaf(zv[4*j],     e4.x, c0);
                c1 = fmaf(zv[4*j + 1], e4.y, c1);
                c2 = fmaf(zv[4*j + 2], e4.z, c2);
                c3 = fmaf(zv[4*j + 3], e4.w, c3);
            }
            float s = __fadd_rn(__fadd_rn(c0, c2), __fadd_rn(c1, c3));
            float d = __fmaf_rn(-2.0f, s, __fadd_rn(zsq, sq[k]));
            if (d < best || (d == best && k < bi)) { best = d; bi = k; }
        }
        atomicAdd(&g_counts[bi], 1);

        // --- fused gather Zq + loss (bit-mimicking fl(z + fl(e - z))) ---
        float* zq = out + 1 + b * 65536 + p;
        const float4* er = (const float4*)(E + bi * 64);
        #pragma unroll
        for (int j = 0; j < 16; j++) {
            float4 e4 = __ldg(er + j);
            float ev[4] = {e4.x, e4.y, e4.z, e4.w};
            #pragma unroll
            for (int m = 0; m < 4; m++) {
                float z = zv[4*j + m];
                float diff = __fsub_rn(ev[m], z);
                ls = fmaf(diff, diff, ls);
                zq[(4*j + m) * 1024] = __fadd_rn(z, diff);
            }
        }
    }

    // --- loss reduction (inactive warps contribute 0) ---
    #pragma unroll
    for (int o = 16; o; o >>= 1) ls += __shfl_xor_sync(0xffffffffu, ls, o);
    __syncthreads();                 // emax reads long done; reuse smx
    if (l == 0) smx[w] = ls;
    __syncthreads();
    if (t == 0) {
        float s = 0.f;
        #pragma unroll
        for (int i = 0; i < NWARP; i++) s += smx[i];
        atomicAdd(&g_loss, (double)s);
        __threadfence();
        int old = atomicAdd(&g_done, 1);
        s_islast = (old == NCTA - 1);
    }
    __syncthreads();

    // --- last CTA: finalize (perplexity + scalars) ---
    if (s_islast) {
        __threadfence();
        float v = 0.f;
        #pragma unroll
        for (int i = 0; i < 2; i++) {
            int k = t + i * 512;
            float cnt = (float)g_counts[k];
            float pr = cnt * (1.0f / 65536.0f);
            v = fmaf(pr, log2f(pr + 1e-10f), v);
        }
        #pragma unroll
        for (int o = 16; o; o >>= 1) v += __shfl_xor_sync(0xffffffffu, v, o);
        if (l == 0) smx[w] = v;
        __syncthreads();
        if (t == 0) {
            float x = 0.f;
            #pragma unroll
            for (int i = 0; i < NWARP; i++) x += smx[i];
            float entropy = -x;
            float perp = exp2f(entropy);
            float lv = (float)(g_loss * (1.0 / 4194304.0));
            out[0] = lv + 0.25f * lv;
            out[1 + NROWS * DIM]     = lv;
            out[1 + NROWS * DIM + 1] = lv;
            out[1 + NROWS * DIM + 2] = perp;
            g_done = 0;              // reset for graph replay determinism
        }
    }
}

// ---------------------------------------------------------------------------
extern "C" void kernel_launch(void* const* d_in, const int* in_sizes, int n_in,
                              void* d_out, int out_size) {
    const float* in = (const float*)d_in[0];
    const float* E  = (const float*)d_in[1];
    float* out = (float*)d_out;

    cudaFuncSetAttribute(vq_main, cudaFuncAttributeMaxDynamicSharedMemorySize,
                         SMEM_SZ);
    prep_kernel<<<32, 32>>>(E);
    vq_main<<<NCTA, THREADS, SMEM_SZ>>>(in, E, out);
}